// round 15
// baseline (speedup 1.0000x reference)
#include <cuda_runtime.h>
#include <cstdint>

#define T_DIM 1024
#define B_DIM 256
#define I_DIM 128
#define H_DIM 256

// Wh tiering in the rec kernel
#define KREG 88                   // k in [0,88): packed dup in registers
#define KSP  48                   // k in [88,136): packed dup in smem
#define KSC  120                  // k in [136,256): scalar in smem [j][k]
#define WSC_STRIDE 124            // floats per j-row (31 float4, conflict-free phases)
#define SP_PAIRS (KSP / 2)        // 24
#define SMEM_WP2_BYTES (SP_PAIRS * 256 * 16)            // 98304
#define SMEM_WSC_BYTES (256 * WSC_STRIDE * 4)           // 126976
#define REC_DYN_SMEM (SMEM_WP2_BYTES + SMEM_WSC_BYTES)  // 225280

// ---------- packed fp32x2 helpers (each lane = independent scalar RN FMA) ----
static __device__ __forceinline__ unsigned long long ffma2(
    unsigned long long a, unsigned long long b, unsigned long long c) {
    unsigned long long d;
    asm("fma.rn.f32x2 %0, %1, %2, %3;" : "=l"(d) : "l"(a), "l"(b), "l"(c));
    return d;
}
static __device__ __forceinline__ unsigned long long packdup(float w) {
    unsigned long long d;
    asm("mov.b64 %0, {%1, %1};" : "=l"(d) : "f"(w));
    return d;
}
static __device__ __forceinline__ float lof(unsigned long long v) {
    return __uint_as_float((unsigned int)(v & 0xffffffffULL));
}
static __device__ __forceinline__ float hif(unsigned long long v) {
    return __uint_as_float((unsigned int)(v >> 32));
}

// ---------- reference-matched tanh: MLIR clamp, FMA-contracted rational ------
static __device__ __forceinline__ float ref_tanh(float x) {
    const float kClamp = 7.99881172180175781f;
    float xc = fminf(fmaxf(x, -kClamp), kClamp);
    float x2 = __fmul_rn(xc, xc);
    float p;
    p = __fmaf_rn(x2, -2.76076847742355e-16f, 2.00018790482477e-13f);
    p = __fmaf_rn(x2, p, -8.60467152213735e-11f);
    p = __fmaf_rn(x2, p,  5.12229709037114e-08f);
    p = __fmaf_rn(x2, p,  1.48572235717979e-05f);
    p = __fmaf_rn(x2, p,  6.37261928875436e-04f);
    p = __fmaf_rn(x2, p,  4.89352455891786e-03f);
    p = __fmul_rn(xc, p);
    float q;
    q = __fmaf_rn(x2, 1.19825839466702e-06f, 1.18534705686654e-04f);
    q = __fmaf_rn(x2, q, 2.26843463243900e-03f);
    q = __fmaf_rn(x2, q, 4.89352518554385e-03f);
    float r = __fdiv_rn(p, q);
    return (fabsf(x) < 0.0004f) ? x : r;
}

// Transposed Wh scratch: g_WhT[k][j] = Wh[j][k]
__device__ float g_WhT[H_DIM * H_DIM];

// ============================================================
// Kernel 1: xproj (f32x2 over batch-row pairs; lane = exact flat ascending-i
// scalar chain + fp32 bias). ALSO: the 16 blocks with blockIdx.x==0 build
// g_WhT (coalesced reads of Wh rows) — removes the separate transpose launch.
// ============================================================
__global__ void __launch_bounds__(256) xproj_kernel(
    const float* __restrict__ X, const float* __restrict__ Wi,
    const float* __restrict__ Wh, const float* __restrict__ bh,
    float* __restrict__ out)
{
    __shared__ __align__(16) float2 xsp[8][I_DIM];

    const int t   = blockIdx.x;
    const int b0  = blockIdx.y * 16;
    const int tid = threadIdx.x;
    const int j   = tid;

    // side job: transpose Wh (16 blocks x 16 rows each)
    if (t == 0) {
        int r0 = blockIdx.y * 16;
#pragma unroll
        for (int r = 0; r < 16; r++) {
            int row = r0 + r;
            g_WhT[tid * H_DIM + row] = Wh[row * H_DIM + tid];
        }
    }

    // stage X pair-transposed
    const float4* X4 = reinterpret_cast<const float4*>(X);
#pragma unroll
    for (int v = 0; v < 2; v++) {
        int lin = tid + v * 256, bb = lin >> 5, i4 = lin & 31;
        float4 val = X4[((size_t)(b0 + bb) * T_DIM + t) * 32 + i4];
        int p = bb >> 1;
        if ((bb & 1) == 0) {
            xsp[p][i4 * 4 + 0].x = val.x; xsp[p][i4 * 4 + 1].x = val.y;
            xsp[p][i4 * 4 + 2].x = val.z; xsp[p][i4 * 4 + 3].x = val.w;
        } else {
            xsp[p][i4 * 4 + 0].y = val.x; xsp[p][i4 * 4 + 1].y = val.y;
            xsp[p][i4 * 4 + 2].y = val.z; xsp[p][i4 * 4 + 3].y = val.w;
        }
    }
    __syncthreads();

    unsigned long long acc[8];
#pragma unroll
    for (int p = 0; p < 8; p++) acc[p] = 0ULL;

    const float4* wrow = reinterpret_cast<const float4*>(Wi + (size_t)j * I_DIM);

#pragma unroll 4
    for (int ig = 0; ig < 32; ig++) {
        float4 w = wrow[ig];
        unsigned long long wx = packdup(w.x), wy = packdup(w.y);
        unsigned long long wz = packdup(w.z), ww = packdup(w.w);
#pragma unroll
        for (int p = 0; p < 8; p++) {
            ulonglong2 A  = *reinterpret_cast<const ulonglong2*>(&xsp[p][ig * 4]);
            ulonglong2 Bv = *reinterpret_cast<const ulonglong2*>(&xsp[p][ig * 4 + 2]);
            acc[p] = ffma2(wx, A.x,  acc[p]);
            acc[p] = ffma2(wy, A.y,  acc[p]);
            acc[p] = ffma2(wz, Bv.x, acc[p]);
            acc[p] = ffma2(ww, Bv.y, acc[p]);
        }
    }

    const float bhj = bh[j];
    size_t base = ((size_t)t * B_DIM + b0) * H_DIM + j;
#pragma unroll
    for (int p = 0; p < 8; p++) {
        out[base + (size_t)(2 * p) * H_DIM]     = __fadd_rn(lof(acc[p]), bhj);
        out[base + (size_t)(2 * p + 1) * H_DIM] = __fadd_rn(hif(acc[p]), bhj);
    }
}

// ============================================================
// Kernel 2: recurrence. 128 CTAs x 256 thr; CTA owns rows (2*blk, 2*blk+1);
// thread = column j, both rows in one f32x2 lane pair (lo=row0, hi=row1).
// Wh tiers: regs (packed dup) / smem packed dup / smem scalar [j][k] row.
// Each lane's value path = flat ascending-k single-acc RN-FMA chain: bitwise
// identical to the reference.
// ============================================================
__global__ void __launch_bounds__(256, 1) rnn_rec_kernel(float* __restrict__ out) {
    extern __shared__ __align__(16) char dynsm[];
    ulonglong2* wp2 = reinterpret_cast<ulonglong2*>(dynsm);           // [SP_PAIRS][256]
    float*      wsc = reinterpret_cast<float*>(dynsm + SMEM_WP2_BYTES); // [256][WSC_STRIDE]
    __shared__ __align__(16) float2 hbuf[2][H_DIM];

    const int j  = threadIdx.x;
    const int b0 = blockIdx.x * 2;

    // tier 1: registers, packed dup
    unsigned long long wp[KREG];
#pragma unroll
    for (int k = 0; k < KREG; k++) wp[k] = packdup(g_WhT[k * H_DIM + j]);

    // tier 2: smem packed dup (coalesced reads; STS.128 per pair)
#pragma unroll
    for (int p = 0; p < SP_PAIRS; p++) {
        int k = KREG + 2 * p;
        ulonglong2 v;
        v.x = packdup(g_WhT[k * H_DIM + j]);
        v.y = packdup(g_WhT[(k + 1) * H_DIM + j]);
        wp2[p * 256 + j] = v;
    }
    // tier 3: smem scalar rows wsc[j][kk] (coalesced LDG, minor STS conflicts)
#pragma unroll 8
    for (int kk = 0; kk < KSC; kk++)
        wsc[j * WSC_STRIDE + kk] = g_WhT[(KREG + KSP + kk) * H_DIM + j];

    hbuf[0][j] = make_float2(0.0f, 0.0f);
    __syncthreads();

    const float4* wsc4 = reinterpret_cast<const float4*>(wsc + j * WSC_STRIDE);

    int cur = 0;
    size_t base = (size_t)b0 * H_DIM + j;

    for (int t = 0; t < T_DIM; t++) {
        float xp0 = out[base];
        float xp1 = out[base + H_DIM];

        const float2* hc = hbuf[cur];
        unsigned long long acc = 0ULL;

        // tier 1: k in [0, KREG)
#pragma unroll
        for (int k = 0; k < KREG; k += 2) {
            ulonglong2 hv = *reinterpret_cast<const ulonglong2*>(&hc[k]);
            acc = ffma2(wp[k],     hv.x, acc);
            acc = ffma2(wp[k + 1], hv.y, acc);
        }
        // tier 2: k in [KREG, KREG+KSP), packed w from smem
#pragma unroll
        for (int p = 0; p < SP_PAIRS; p++) {
            int k = KREG + 2 * p;
            ulonglong2 hv = *reinterpret_cast<const ulonglong2*>(&hc[k]);
            ulonglong2 wv = wp2[p * 256 + j];
            acc = ffma2(wv.x, hv.x, acc);
            acc = ffma2(wv.y, hv.y, acc);
        }
        // tier 3: k in [KREG+KSP, 256), scalar chains continue each lane
        float a0 = lof(acc), a1 = hif(acc);
#pragma unroll
        for (int g = 0; g < KSC / 4; g++) {
            int k = KREG + KSP + 4 * g;
            float4 w4 = wsc4[g];                                        // 4 w's
            float4 hA = *reinterpret_cast<const float4*>(&hc[k]);       // h0,h1 @ k,k+1
            float4 hB = *reinterpret_cast<const float4*>(&hc[k + 2]);   // h0,h1 @ k+2,k+3
            a0 = __fmaf_rn(w4.x, hA.x, a0);  a1 = __fmaf_rn(w4.x, hA.y, a1);
            a0 = __fmaf_rn(w4.y, hA.z, a0);  a1 = __fmaf_rn(w4.y, hA.w, a1);
            a0 = __fmaf_rn(w4.z, hB.x, a0);  a1 = __fmaf_rn(w4.z, hB.y, a1);
            a0 = __fmaf_rn(w4.w, hB.z, a0);  a1 = __fmaf_rn(w4.w, hB.w, a1);
        }

        float hn0 = ref_tanh(__fadd_rn(xp0, a0));
        float hn1 = ref_tanh(__fadd_rn(xp1, a1));

        int nxt = cur ^ 1;
        hbuf[nxt][j] = make_float2(hn0, hn1);
        out[base]         = hn0;
        out[base + H_DIM] = hn1;
        __syncthreads();
        cur = nxt;
        base += (size_t)B_DIM * H_DIM;
    }
}

// ============================================================
extern "C" void kernel_launch(void* const* d_in, const int* in_sizes, int n_in,
                              void* d_out, int out_size) {
    const float* X  = nullptr; const float* Wi = nullptr;
    const float* Wh = nullptr; const float* bh = nullptr;
    for (int i = 0; i < n_in; i++) {
        switch (in_sizes[i]) {
            case B_DIM * T_DIM * I_DIM: X  = (const float*)d_in[i]; break;
            case H_DIM * I_DIM:         Wi = (const float*)d_in[i]; break;
            case H_DIM * H_DIM:         Wh = (const float*)d_in[i]; break;
            case H_DIM:                 bh = (const float*)d_in[i]; break;
            default: break;
        }
    }
    float* out = (float*)d_out;

    cudaFuncSetAttribute(rnn_rec_kernel,
                         cudaFuncAttributeMaxDynamicSharedMemorySize, REC_DYN_SMEM);

    xproj_kernel<<<dim3(T_DIM, B_DIM / 16), 256>>>(X, Wi, Wh, bh, out);
    rnn_rec_kernel<<<B_DIM / 2, 256, REC_DYN_SMEM>>>(out);
}

// round 16
// speedup vs baseline: 1.3026x; 1.3026x over previous
#include <cuda_runtime.h>
#include <cstdint>

#define T_DIM 1024
#define B_DIM 256
#define I_DIM 128
#define H_DIM 256

#define KR 160                      // w[k] k<160: scalar registers
#define KS (H_DIM - KR)             // 96: scalar smem [k][j]
#define REC_DYN_SMEM (KS * H_DIM * 4)   // 98304 B

// ---------- packed fp32x2 helpers (xproj only) ----------
static __device__ __forceinline__ unsigned long long ffma2(
    unsigned long long a, unsigned long long b, unsigned long long c) {
    unsigned long long d;
    asm("fma.rn.f32x2 %0, %1, %2, %3;" : "=l"(d) : "l"(a), "l"(b), "l"(c));
    return d;
}
static __device__ __forceinline__ unsigned long long packdup(float w) {
    unsigned long long d;
    asm("mov.b64 %0, {%1, %1};" : "=l"(d) : "f"(w));
    return d;
}
static __device__ __forceinline__ float lof(unsigned long long v) {
    return __uint_as_float((unsigned int)(v & 0xffffffffULL));
}
static __device__ __forceinline__ float hif(unsigned long long v) {
    return __uint_as_float((unsigned int)(v >> 32));
}

// ---------- reference-matched tanh: MLIR clamp, FMA-contracted rational ------
static __device__ __forceinline__ float ref_tanh(float x) {
    const float kClamp = 7.99881172180175781f;
    float xc = fminf(fmaxf(x, -kClamp), kClamp);
    float x2 = __fmul_rn(xc, xc);
    float p;
    p = __fmaf_rn(x2, -2.76076847742355e-16f, 2.00018790482477e-13f);
    p = __fmaf_rn(x2, p, -8.60467152213735e-11f);
    p = __fmaf_rn(x2, p,  5.12229709037114e-08f);
    p = __fmaf_rn(x2, p,  1.48572235717979e-05f);
    p = __fmaf_rn(x2, p,  6.37261928875436e-04f);
    p = __fmaf_rn(x2, p,  4.89352455891786e-03f);
    p = __fmul_rn(xc, p);
    float q;
    q = __fmaf_rn(x2, 1.19825839466702e-06f, 1.18534705686654e-04f);
    q = __fmaf_rn(x2, q, 2.26843463243900e-03f);
    q = __fmaf_rn(x2, q, 4.89352518554385e-03f);
    float r = __fdiv_rn(p, q);
    return (fabsf(x) < 0.0004f) ? x : r;
}

// Transposed Wh scratch: g_WhT[k][j] = Wh[j][k]
__device__ float g_WhT[H_DIM * H_DIM];

// ============================================================
// Kernel 1: xproj (f32x2 over batch-row pairs; each lane = exact flat
// ascending-i scalar chain + fp32 bias). blockIdx.x==0 blocks also build
// g_WhT (no separate transpose launch).
// ============================================================
__global__ void __launch_bounds__(256) xproj_kernel(
    const float* __restrict__ X, const float* __restrict__ Wi,
    const float* __restrict__ Wh, const float* __restrict__ bh,
    float* __restrict__ out)
{
    __shared__ __align__(16) float2 xsp[8][I_DIM];

    const int t   = blockIdx.x;
    const int b0  = blockIdx.y * 16;
    const int tid = threadIdx.x;
    const int j   = tid;

    if (t == 0) {
        int r0 = blockIdx.y * 16;
#pragma unroll
        for (int r = 0; r < 16; r++) {
            int row = r0 + r;
            g_WhT[tid * H_DIM + row] = Wh[row * H_DIM + tid];
        }
    }

    const float4* X4 = reinterpret_cast<const float4*>(X);
#pragma unroll
    for (int v = 0; v < 2; v++) {
        int lin = tid + v * 256, bb = lin >> 5, i4 = lin & 31;
        float4 val = X4[((size_t)(b0 + bb) * T_DIM + t) * 32 + i4];
        int p = bb >> 1;
        if ((bb & 1) == 0) {
            xsp[p][i4 * 4 + 0].x = val.x; xsp[p][i4 * 4 + 1].x = val.y;
            xsp[p][i4 * 4 + 2].x = val.z; xsp[p][i4 * 4 + 3].x = val.w;
        } else {
            xsp[p][i4 * 4 + 0].y = val.x; xsp[p][i4 * 4 + 1].y = val.y;
            xsp[p][i4 * 4 + 2].y = val.z; xsp[p][i4 * 4 + 3].y = val.w;
        }
    }
    __syncthreads();

    unsigned long long acc[8];
#pragma unroll
    for (int p = 0; p < 8; p++) acc[p] = 0ULL;

    const float4* wrow = reinterpret_cast<const float4*>(Wi + (size_t)j * I_DIM);

#pragma unroll 4
    for (int ig = 0; ig < 32; ig++) {
        float4 w = wrow[ig];
        unsigned long long wx = packdup(w.x), wy = packdup(w.y);
        unsigned long long wz = packdup(w.z), ww = packdup(w.w);
#pragma unroll
        for (int p = 0; p < 8; p++) {
            ulonglong2 A  = *reinterpret_cast<const ulonglong2*>(&xsp[p][ig * 4]);
            ulonglong2 Bv = *reinterpret_cast<const ulonglong2*>(&xsp[p][ig * 4 + 2]);
            acc[p] = ffma2(wx, A.x,  acc[p]);
            acc[p] = ffma2(wy, A.y,  acc[p]);
            acc[p] = ffma2(wz, Bv.x, acc[p]);
            acc[p] = ffma2(ww, Bv.y, acc[p]);
        }
    }

    const float bhj = bh[j];
    size_t base = ((size_t)t * B_DIM + b0) * H_DIM + j;
#pragma unroll
    for (int p = 0; p < 8; p++) {
        out[base + (size_t)(2 * p) * H_DIM]     = __fadd_rn(lof(acc[p]), bhj);
        out[base + (size_t)(2 * p + 1) * H_DIM] = __fadd_rn(hif(acc[p]), bhj);
    }
}

// ============================================================
// Kernel 2: recurrence. 128 CTAs x 256 thr; CTA owns rows (2*blk, 2*blk+1).
// Thread j: TWO scalar chains (a0=row0, a1=row1), flat ascending k — each is
// bitwise the reference chain. w[j][k]: k<KR in 160 scalar regs; k>=KR in
// smem [k][j] (dense conflict-free LDS.32). h ping-pong float2; consumed as
// float4 (2 k's per LDS.128 broadcast). xp prefetched one step ahead.
// ============================================================
__global__ void __launch_bounds__(256, 1) rnn_rec_kernel(float* __restrict__ out) {
    extern __shared__ float wsm[];                    // [KS][256]
    __shared__ __align__(16) float2 hbuf[2][H_DIM];

    const int j  = threadIdx.x;
    const int b0 = blockIdx.x * 2;

    // tier 1: scalar regs
    float wr[KR];
#pragma unroll
    for (int k = 0; k < KR; k++) wr[k] = g_WhT[k * H_DIM + j];
    // tier 2: smem [k][j], coalesced both ways
#pragma unroll
    for (int kk = 0; kk < KS; kk++)
        wsm[kk * H_DIM + j] = g_WhT[(KR + kk) * H_DIM + j];

    hbuf[0][j] = make_float2(0.0f, 0.0f);
    __syncthreads();

    int cur = 0;
    size_t base = (size_t)b0 * H_DIM + j;
    const size_t step = (size_t)B_DIM * H_DIM;

    float xp0 = out[base];
    float xp1 = out[base + H_DIM];

    for (int t = 0; t < T_DIM; t++) {
        // prefetch next step's xp (clamped at the last step)
        size_t nbase = (t < T_DIM - 1) ? base + step : base;
        float nxp0 = out[nbase];
        float nxp1 = out[nbase + H_DIM];

        const float4* hc4 = reinterpret_cast<const float4*>(hbuf[cur]);

        float a0 = 0.0f, a1 = 0.0f;

        // tier 1: k in [0, KR), w from registers; float4 = 2 k's of (h0,h1)
#pragma unroll
        for (int g = 0; g < KR / 2; g++) {
            float4 h = hc4[g];
            a0 = __fmaf_rn(wr[2 * g],     h.x, a0);
            a1 = __fmaf_rn(wr[2 * g],     h.y, a1);
            a0 = __fmaf_rn(wr[2 * g + 1], h.z, a0);
            a1 = __fmaf_rn(wr[2 * g + 1], h.w, a1);
        }
        // tier 2: k in [KR, 256), w from smem (dense LDS.32 per k)
#pragma unroll
        for (int s = 0; s < KS / 2; s++) {
            float4 h = hc4[KR / 2 + s];
            float w0 = wsm[(2 * s) * H_DIM + j];
            float w1 = wsm[(2 * s + 1) * H_DIM + j];
            a0 = __fmaf_rn(w0, h.x, a0);
            a1 = __fmaf_rn(w0, h.y, a1);
            a0 = __fmaf_rn(w1, h.z, a0);
            a1 = __fmaf_rn(w1, h.w, a1);
        }

        float hn0 = ref_tanh(__fadd_rn(xp0, a0));
        float hn1 = ref_tanh(__fadd_rn(xp1, a1));

        int nxt = cur ^ 1;
        hbuf[nxt][j] = make_float2(hn0, hn1);
        out[base]         = hn0;
        out[base + H_DIM] = hn1;
        __syncthreads();

        cur  = nxt;
        base = nbase;
        xp0  = nxp0;
        xp1  = nxp1;
    }
}

// ============================================================
extern "C" void kernel_launch(void* const* d_in, const int* in_sizes, int n_in,
                              void* d_out, int out_size) {
    const float* X  = nullptr; const float* Wi = nullptr;
    const float* Wh = nullptr; const float* bh = nullptr;
    for (int i = 0; i < n_in; i++) {
        switch (in_sizes[i]) {
            case B_DIM * T_DIM * I_DIM: X  = (const float*)d_in[i]; break;
            case H_DIM * I_DIM:         Wi = (const float*)d_in[i]; break;
            case H_DIM * H_DIM:         Wh = (const float*)d_in[i]; break;
            case H_DIM:                 bh = (const float*)d_in[i]; break;
            default: break;
        }
    }
    float* out = (float*)d_out;

    cudaFuncSetAttribute(rnn_rec_kernel,
                         cudaFuncAttributeMaxDynamicSharedMemorySize, REC_DYN_SMEM);

    xproj_kernel<<<dim3(T_DIM, B_DIM / 16), 256>>>(X, Wi, Wh, bh, out);
    rnn_rec_kernel<<<B_DIM / 2, 256, REC_DYN_SMEM>>>(out);
}

// round 17
// speedup vs baseline: 1.3675x; 1.0499x over previous
#include <cuda_runtime.h>
#include <cstdint>

#define T_DIM 1024
#define B_DIM 256
#define I_DIM 128
#define H_DIM 256

#define KR 76                         // per-column k's in registers (even!)
#define KS (H_DIM - KR)               // 180 per-column k's in smem [k][j]
#define REC_DYN_SMEM (KS * H_DIM * 4) // 184320 B

// ---------- packed fp32x2 helpers (xproj only) ----------
static __device__ __forceinline__ unsigned long long ffma2(
    unsigned long long a, unsigned long long b, unsigned long long c) {
    unsigned long long d;
    asm("fma.rn.f32x2 %0, %1, %2, %3;" : "=l"(d) : "l"(a), "l"(b), "l"(c));
    return d;
}
static __device__ __forceinline__ unsigned long long packdup(float w) {
    unsigned long long d;
    asm("mov.b64 %0, {%1, %1};" : "=l"(d) : "f"(w));
    return d;
}
static __device__ __forceinline__ float lof(unsigned long long v) {
    return __uint_as_float((unsigned int)(v & 0xffffffffULL));
}
static __device__ __forceinline__ float hif(unsigned long long v) {
    return __uint_as_float((unsigned int)(v >> 32));
}

// ---------- reference-matched tanh: MLIR clamp, FMA-contracted rational ------
static __device__ __forceinline__ float ref_tanh(float x) {
    const float kClamp = 7.99881172180175781f;
    float xc = fminf(fmaxf(x, -kClamp), kClamp);
    float x2 = __fmul_rn(xc, xc);
    float p;
    p = __fmaf_rn(x2, -2.76076847742355e-16f, 2.00018790482477e-13f);
    p = __fmaf_rn(x2, p, -8.60467152213735e-11f);
    p = __fmaf_rn(x2, p,  5.12229709037114e-08f);
    p = __fmaf_rn(x2, p,  1.48572235717979e-05f);
    p = __fmaf_rn(x2, p,  6.37261928875436e-04f);
    p = __fmaf_rn(x2, p,  4.89352455891786e-03f);
    p = __fmul_rn(xc, p);
    float q;
    q = __fmaf_rn(x2, 1.19825839466702e-06f, 1.18534705686654e-04f);
    q = __fmaf_rn(x2, q, 2.26843463243900e-03f);
    q = __fmaf_rn(x2, q, 4.89352518554385e-03f);
    float r = __fdiv_rn(p, q);
    return (fabsf(x) < 0.0004f) ? x : r;
}

// Transposed Wh scratch: g_WhT[k][j] = Wh[j][k]
__device__ float g_WhT[H_DIM * H_DIM];

// ============================================================
// Kernel 1: xproj (f32x2 over batch-row pairs; each lane = exact flat
// ascending-i scalar chain + fp32 bias). blockIdx.x==0 blocks also build
// g_WhT (no separate transpose launch).
// ============================================================
__global__ void __launch_bounds__(256) xproj_kernel(
    const float* __restrict__ X, const float* __restrict__ Wi,
    const float* __restrict__ Wh, const float* __restrict__ bh,
    float* __restrict__ out)
{
    __shared__ __align__(16) float2 xsp[8][I_DIM];

    const int t   = blockIdx.x;
    const int b0  = blockIdx.y * 16;
    const int tid = threadIdx.x;
    const int j   = tid;

    if (t == 0) {
        int r0 = blockIdx.y * 16;
#pragma unroll
        for (int r = 0; r < 16; r++) {
            int row = r0 + r;
            g_WhT[tid * H_DIM + row] = Wh[row * H_DIM + tid];
        }
    }

    const float4* X4 = reinterpret_cast<const float4*>(X);
#pragma unroll
    for (int v = 0; v < 2; v++) {
        int lin = tid + v * 256, bb = lin >> 5, i4 = lin & 31;
        float4 val = X4[((size_t)(b0 + bb) * T_DIM + t) * 32 + i4];
        int p = bb >> 1;
        if ((bb & 1) == 0) {
            xsp[p][i4 * 4 + 0].x = val.x; xsp[p][i4 * 4 + 1].x = val.y;
            xsp[p][i4 * 4 + 2].x = val.z; xsp[p][i4 * 4 + 3].x = val.w;
        } else {
            xsp[p][i4 * 4 + 0].y = val.x; xsp[p][i4 * 4 + 1].y = val.y;
            xsp[p][i4 * 4 + 2].y = val.z; xsp[p][i4 * 4 + 3].y = val.w;
        }
    }
    __syncthreads();

    unsigned long long acc[8];
#pragma unroll
    for (int p = 0; p < 8; p++) acc[p] = 0ULL;

    const float4* wrow = reinterpret_cast<const float4*>(Wi + (size_t)j * I_DIM);

#pragma unroll 4
    for (int ig = 0; ig < 32; ig++) {
        float4 w = wrow[ig];
        unsigned long long wx = packdup(w.x), wy = packdup(w.y);
        unsigned long long wz = packdup(w.z), ww = packdup(w.w);
#pragma unroll
        for (int p = 0; p < 8; p++) {
            ulonglong2 A  = *reinterpret_cast<const ulonglong2*>(&xsp[p][ig * 4]);
            ulonglong2 Bv = *reinterpret_cast<const ulonglong2*>(&xsp[p][ig * 4 + 2]);
            acc[p] = ffma2(wx, A.x,  acc[p]);
            acc[p] = ffma2(wy, A.y,  acc[p]);
            acc[p] = ffma2(wz, Bv.x, acc[p]);
            acc[p] = ffma2(ww, Bv.y, acc[p]);
        }
    }

    const float bhj = bh[j];
    size_t base = ((size_t)t * B_DIM + b0) * H_DIM + j;
#pragma unroll
    for (int p = 0; p < 8; p++) {
        out[base + (size_t)(2 * p) * H_DIM]     = __fadd_rn(lof(acc[p]), bhj);
        out[base + (size_t)(2 * p + 1) * H_DIM] = __fadd_rn(hif(acc[p]), bhj);
    }
}

// ============================================================
// Kernel 2: recurrence. 128 CTAs x 128 thr (4 warps); CTA owns batch rows
// (2*blk, 2*blk+1). Thread tj owns columns j0=tj, j1=tj+128 and BOTH rows:
// 4 independent scalar chains (ILP 4), each the exact flat ascending-k
// single-acc RN-FMA chain. h loads shared across the thread's two columns
// (halves broadcast traffic vs the 256-thread shape). w: KR k's per column
// in regs; KS per column in smem [k][j] (lane-dense LDS.32).
// ============================================================
__global__ void __launch_bounds__(128, 1) rnn_rec_kernel(float* __restrict__ out) {
    extern __shared__ float wsm[];                    // [KS][256]
    __shared__ __align__(16) float2 hbuf[2][H_DIM];

    const int tj = threadIdx.x;        // 0..127
    const int j0 = tj;
    const int j1 = tj + 128;
    const int b0 = blockIdx.x * 2;

    // w registers: KR k's for each of the two columns
    float wA[KR], wB[KR];
#pragma unroll
    for (int k = 0; k < KR; k++) {
        wA[k] = g_WhT[k * H_DIM + j0];
        wB[k] = g_WhT[k * H_DIM + j1];
    }
    // w smem: [k][j] for k in [KR,256), all 256 columns (each thread stages 2)
#pragma unroll
    for (int kk = 0; kk < KS; kk++) {
        wsm[kk * H_DIM + j0] = g_WhT[(KR + kk) * H_DIM + j0];
        wsm[kk * H_DIM + j1] = g_WhT[(KR + kk) * H_DIM + j1];
    }

    hbuf[0][j0] = make_float2(0.0f, 0.0f);
    hbuf[0][j1] = make_float2(0.0f, 0.0f);
    __syncthreads();

    int cur = 0;
    size_t base = (size_t)b0 * H_DIM;
    const size_t step = (size_t)B_DIM * H_DIM;

    // xp prefetch (4 values: 2 cols x 2 rows)
    float xp00 = out[base + j0],         xp01 = out[base + H_DIM + j0];
    float xp10 = out[base + j1],         xp11 = out[base + H_DIM + j1];

    for (int t = 0; t < T_DIM; t++) {
        size_t nbase = (t < T_DIM - 1) ? base + step : base;
        float nxp00 = out[nbase + j0],   nxp01 = out[nbase + H_DIM + j0];
        float nxp10 = out[nbase + j1],   nxp11 = out[nbase + H_DIM + j1];

        const float4* hc4 = reinterpret_cast<const float4*>(hbuf[cur]);

        float a00 = 0.0f, a01 = 0.0f;   // col j0: row0, row1
        float a10 = 0.0f, a11 = 0.0f;   // col j1: row0, row1

        // tier 1: k in [0, KR), w in regs; float4 = (h0[k],h1[k],h0[k+1],h1[k+1])
#pragma unroll
        for (int g = 0; g < KR / 2; g++) {
            float4 h = hc4[g];
            float wa0 = wA[2 * g], wa1 = wA[2 * g + 1];
            float wb0 = wB[2 * g], wb1 = wB[2 * g + 1];
            a00 = __fmaf_rn(wa0, h.x, a00);  a01 = __fmaf_rn(wa0, h.y, a01);
            a10 = __fmaf_rn(wb0, h.x, a10);  a11 = __fmaf_rn(wb0, h.y, a11);
            a00 = __fmaf_rn(wa1, h.z, a00);  a01 = __fmaf_rn(wa1, h.w, a01);
            a10 = __fmaf_rn(wb1, h.z, a10);  a11 = __fmaf_rn(wb1, h.w, a11);
        }
        // tier 2: k in [KR, 256), w from smem (dense LDS.32 per column)
#pragma unroll
        for (int s = 0; s < KS / 2; s++) {
            float4 h = hc4[KR / 2 + s];
            float wa0 = wsm[(2 * s) * H_DIM + j0];
            float wb0 = wsm[(2 * s) * H_DIM + j1];
            float wa1 = wsm[(2 * s + 1) * H_DIM + j0];
            float wb1 = wsm[(2 * s + 1) * H_DIM + j1];
            a00 = __fmaf_rn(wa0, h.x, a00);  a01 = __fmaf_rn(wa0, h.y, a01);
            a10 = __fmaf_rn(wb0, h.x, a10);  a11 = __fmaf_rn(wb0, h.y, a11);
            a00 = __fmaf_rn(wa1, h.z, a00);  a01 = __fmaf_rn(wa1, h.w, a01);
            a10 = __fmaf_rn(wb1, h.z, a10);  a11 = __fmaf_rn(wb1, h.w, a11);
        }

        float hn00 = ref_tanh(__fadd_rn(xp00, a00));
        float hn01 = ref_tanh(__fadd_rn(xp01, a01));
        float hn10 = ref_tanh(__fadd_rn(xp10, a10));
        float hn11 = ref_tanh(__fadd_rn(xp11, a11));

        int nxt = cur ^ 1;
        hbuf[nxt][j0] = make_float2(hn00, hn01);
        hbuf[nxt][j1] = make_float2(hn10, hn11);
        out[base + j0]          = hn00;
        out[base + H_DIM + j0]  = hn01;
        out[base + j1]          = hn10;
        out[base + H_DIM + j1]  = hn11;
        __syncthreads();

        cur  = nxt;
        base = nbase;
        xp00 = nxp00; xp01 = nxp01; xp10 = nxp10; xp11 = nxp11;
    }
}

// ============================================================
extern "C" void kernel_launch(void* const* d_in, const int* in_sizes, int n_in,
                              void* d_out, int out_size) {
    const float* X  = nullptr; const float* Wi = nullptr;
    const float* Wh = nullptr; const float* bh = nullptr;
    for (int i = 0; i < n_in; i++) {
        switch (in_sizes[i]) {
            case B_DIM * T_DIM * I_DIM: X  = (const float*)d_in[i]; break;
            case H_DIM * I_DIM:         Wi = (const float*)d_in[i]; break;
            case H_DIM * H_DIM:         Wh = (const float*)d_in[i]; break;
            case H_DIM:                 bh = (const float*)d_in[i]; break;
            default: break;
        }
    }
    float* out = (float*)d_out;

    cudaFuncSetAttribute(rnn_rec_kernel,
                         cudaFuncAttributeMaxDynamicSharedMemorySize, REC_DYN_SMEM);

    xproj_kernel<<<dim3(T_DIM, B_DIM / 16), 256>>>(X, Wi, Wh, bh, out);
    rnn_rec_kernel<<<B_DIM / 2, 128, REC_DYN_SMEM>>>(out);
}